// round 8
// baseline (speedup 1.0000x reference)
#include <cuda_runtime.h>

#define TPB     256
#define NBLOCKS 592        // 148 SMs x 4 CTAs/SM

// Duplicated-weight layout (each entry is {w, w}) in constant memory:
// [0:24)  W1 (3x8 row-major)   [24:32) b1
// [32:64) W2 (8x4 row-major)   [64:68) b2
// [68:72) W3                   [72] b3   [73] w
__device__    float2 g_stage2[80];
__constant__  float2 cw2[80];

__global__ void gather_weights(
    const float* __restrict__ W1, const float* __restrict__ b1,
    const float* __restrict__ W2, const float* __restrict__ b2,
    const float* __restrict__ W3, const float* __restrict__ b3,
    const float* __restrict__ w)
{
    const int i = threadIdx.x;
    float s;
    if (i < 24)       s = W1[i];
    else if (i < 32)  s = b1[i - 24];
    else if (i < 64)  s = W2[i - 32];
    else if (i < 68)  s = b2[i - 64];
    else if (i < 72)  s = W3[i - 68];
    else if (i == 72) s = b3[0];
    else if (i == 73) s = w[0];
    else return;
    g_stage2[i] = make_float2(s, s);
}

// ---- packed f32x2 helpers (both MLP rows in one instruction) ----
__device__ __forceinline__ unsigned long long f2ll(float2 v) {
    unsigned long long r;
    asm("mov.b64 %0, {%1, %2};" : "=l"(r) : "f"(v.x), "f"(v.y));
    return r;
}
__device__ __forceinline__ float2 ll2f(unsigned long long r) {
    float2 v;
    asm("mov.b64 {%0, %1}, %2;" : "=f"(v.x), "=f"(v.y) : "l"(r));
    return v;
}
__device__ __forceinline__ float2 fma2(float2 a, float2 b, float2 c) {
    unsigned long long rd;
    asm("fma.rn.f32x2 %0, %1, %2, %3;"
        : "=l"(rd) : "l"(f2ll(a)), "l"(f2ll(b)), "l"(f2ll(c)));
    return ll2f(rd);
}
__device__ __forceinline__ float2 add2(float2 a, float2 b) {
    unsigned long long rd;
    asm("add.rn.f32x2 %0, %1, %2;" : "=l"(rd) : "l"(f2ll(a)), "l"(f2ll(b)));
    return ll2f(rd);
}
__device__ __forceinline__ float2 mul2(float2 a, float2 b) {
    unsigned long long rd;
    asm("mul.rn.f32x2 %0, %1, %2;" : "=l"(rd) : "l"(f2ll(a)), "l"(f2ll(b)));
    return ll2f(rd);
}
__device__ __forceinline__ float tanha(float x) {
    float y;
    asm("tanh.approx.f32 %0, %1;" : "=f"(y) : "f"(x));
    return y;
}
__device__ __forceinline__ float2 tanh2(float2 a) {
    return make_float2(tanha(a.x), tanha(a.y));
}
__device__ __forceinline__ float2 sin2(float2 a) {
    return make_float2(__sinf(a.x), __sinf(a.y));
}

// Evaluate the model for TWO rows at once: row0=(x0.x,x1.x), row1=(x0.y,x1.y)
__device__ __forceinline__ float2 eval_pair(float2 x0, float2 x1) {
    // quantum feature: sin(x0) * sin(x1 + w)   (both rows)
    const float2 q = mul2(sin2(x0), sin2(add2(x1, cw2[73])));

    float2 h1[8];
#pragma unroll
    for (int j = 0; j < 8; ++j) {
        float2 a = fma2(cw2[0 * 8 + j], x0, cw2[24 + j]);
        a = fma2(cw2[1 * 8 + j], x1, a);
        a = fma2(cw2[2 * 8 + j], q, a);
        h1[j] = tanh2(a);
    }

    float2 h2[4];
#pragma unroll
    for (int j = 0; j < 4; ++j) {
        float2 a = cw2[64 + j];
#pragma unroll
        for (int i = 0; i < 8; ++i) a = fma2(h1[i], cw2[32 + i * 4 + j], a);
        h2[j] = tanh2(a);
    }

    float2 o = cw2[72];
#pragma unroll
    for (int j = 0; j < 4; ++j) o = fma2(h2[j], cw2[68 + j], o);
    return o;
}

__device__ __forceinline__ float eval_row(float x0, float x1) {
    const float q = __sinf(x0) * __sinf(x1 + cw2[73].x);
    float h1[8];
#pragma unroll
    for (int j = 0; j < 8; ++j) {
        float a = fmaf(cw2[0 * 8 + j].x, x0, cw2[24 + j].x);
        a = fmaf(cw2[1 * 8 + j].x, x1, a);
        a = fmaf(cw2[2 * 8 + j].x, q, a);
        h1[j] = tanha(a);
    }
    float h2[4];
#pragma unroll
    for (int j = 0; j < 4; ++j) {
        float a = cw2[64 + j].x;
#pragma unroll
        for (int i = 0; i < 8; ++i) a = fmaf(h1[i], cw2[32 + i * 4 + j].x, a);
        h2[j] = tanha(a);
    }
    float o = cw2[72].x;
#pragma unroll
    for (int j = 0; j < 4; ++j) o = fmaf(h2[j], cw2[68 + j].x, o);
    return o;
}

__global__ void __launch_bounds__(TPB, 4) qnn_kernel(
    const float4* __restrict__ in,   // 2 rows per float4
    float2*       __restrict__ out,  // 2 outputs per float2
    int npairs, int nrows,
    const float* __restrict__ in_scalar, float* __restrict__ out_scalar)
{
    const int t      = blockIdx.x * TPB + threadIdx.x;
    const int stride = NBLOCKS * TPB;

    for (int p = t; p < npairs; p += stride) {
        const float4 v = __ldg(in + p);
        // lane packing: .x = row0, .y = row1
        out[p] = eval_pair(make_float2(v.x, v.z), make_float2(v.y, v.w));
    }

    // odd trailing row
    if ((nrows & 1) && t == 0) {
        const float x0 = __ldg(in_scalar + (nrows - 1) * 2);
        const float x1 = __ldg(in_scalar + (nrows - 1) * 2 + 1);
        out_scalar[nrows - 1] = eval_row(x0, x1);
    }
}

extern "C" void kernel_launch(void* const* d_in, const int* in_sizes, int n_in,
                              void* d_out, int out_size)
{
    const float* in = (const float*)d_in[0];
    const int nrows  = in_sizes[0] / 2;
    const int npairs = nrows / 2;

    // Stage duplicated weights into __constant__ (kernel + async D2D memcpy; capturable)
    gather_weights<<<1, 128>>>(
        (const float*)d_in[1], (const float*)d_in[2],
        (const float*)d_in[3], (const float*)d_in[4],
        (const float*)d_in[5], (const float*)d_in[6],
        (const float*)d_in[7]);
    void* stage_addr = nullptr;
    cudaGetSymbolAddress(&stage_addr, g_stage2);
    cudaMemcpyToSymbolAsync(cw2, stage_addr, 80 * sizeof(float2), 0,
                            cudaMemcpyDeviceToDevice, 0);

    qnn_kernel<<<NBLOCKS, TPB>>>(
        (const float4*)in, (float2*)d_out,
        npairs, nrows,
        in, (float*)d_out);
}